// round 7
// baseline (speedup 1.0000x reference)
#include <cuda_runtime.h>

#define N_NODES    1000000
#define N_EDGES    16000000
#define NUM_GRAPHS 64
#define LATENT     128
#define EBLOCKS    3125      // persistent blocks
#define EITERS     5         // 3125 * 128 * 5 * 8 = 16M edges exactly
#define PAIRS_PB   160       // 500,000 node-pairs / 3125 blocks

// Global accumulators (zero-initialized at module load; the final block
// re-zeros everything so each graph replay starts clean).
__device__ double   g_recon;
__device__ double   g_sumd2;
__device__ double   g_sumlen;
__device__ double   g_kl;
__device__ float    g_gsum[2 * NUM_GRAPHS];
__device__ float    g_gcnt[NUM_GRAPHS];
__device__ unsigned g_count;

// Warp-aggregated node-pair accumulate: pair idx -> recon partial (returned,
// warp-reduced, valid in lane 0) + drift segment sums (global atomics).
// Requires: full warp, 32 consecutive pair indices.
__device__ __forceinline__ float node_pairs(const float4* __restrict__ pred4,
                                            const float4* __restrict__ tgt4,
                                            const int2*  __restrict__ batch2,
                                            int idx, int lane) {
    const unsigned FULL = 0xffffffffu;
    float4 p = pred4[idx];
    float4 q = tgt4[idx];
    int2   b = batch2[idx];

    float dx0 = p.x - q.x, dy0 = p.y - q.y;
    float dx1 = p.z - q.z, dy1 = p.w - q.w;
    float rec = dx0 * dx0 + dy0 * dy0 + dx1 * dx1 + dy1 * dy1;
    #pragma unroll
    for (int o = 16; o > 0; o >>= 1)
        rec += __shfl_down_sync(FULL, rec, o);

    int g0   = __shfl_sync(FULL, b.x, 0);
    bool uni = __all_sync(FULL, (b.x == g0) && (b.y == g0));
    if (uni) {
        float sx = p.x + p.z;
        float sy = p.y + p.w;
        #pragma unroll
        for (int o = 16; o > 0; o >>= 1) {
            sx += __shfl_down_sync(FULL, sx, o);
            sy += __shfl_down_sync(FULL, sy, o);
        }
        if (lane == 0) {
            atomicAdd(&g_gsum[2 * g0],     sx);
            atomicAdd(&g_gsum[2 * g0 + 1], sy);
            atomicAdd(&g_gcnt[g0], 64.f);          // 32 lanes x 2 nodes
        }
    } else {
        // boundary warp (graph id changes inside warp) — rare
        atomicAdd(&g_gsum[2 * b.x],     p.x);
        atomicAdd(&g_gsum[2 * b.x + 1], p.y);
        atomicAdd(&g_gcnt[b.x], 1.f);
        atomicAdd(&g_gsum[2 * b.y],     p.z);
        atomicAdd(&g_gsum[2 * b.y + 1], p.w);
        atomicAdd(&g_gcnt[b.y], 1.f);
        __threadfence();   // order these atomics before the done-counter
    }
    return rec;
}

__global__ void __launch_bounds__(128)
fused_kernel(const float4* __restrict__ pred4,
             const float4* __restrict__ tgt4,
             const int2*  __restrict__ batch2,
             const int4*  __restrict__ ei,
             const int4*  __restrict__ ej,
             const float2* __restrict__ pred,
             const float* __restrict__ mu,
             const float* __restrict__ logvar,
             const int*  __restrict__ epoch,
             float* __restrict__ out) {
    const int tid = threadIdx.x;
    const int bid = blockIdx.x;
    const int l   = tid & 31;
    const int w   = tid >> 5;
    const unsigned FULL = 0xffffffffu;

    __shared__ float sred[5];      // recon partials (4 warps + warp0 extra)
    __shared__ float smd2[4], smln[4];

    // ---- prefetch iter-0 edge indices (DRAM, long latency) ----
    int g = bid * 128 + tid;
    int4 na0 = ei[2 * g], na1 = ei[2 * g + 1];
    int4 nb0 = ej[2 * g], nb1 = ej[2 * g + 1];

    // ---- node pass: 160 consecutive pairs per block ----
    {
        float rec = node_pairs(pred4, tgt4, batch2, bid * PAIRS_PB + tid, l);
        if (l == 0) sred[w] = rec;
        if (tid < 32) {
            float rec2 = node_pairs(pred4, tgt4, batch2,
                                    bid * PAIRS_PB + 128 + tid, l);
            if (l == 0) sred[4] = rec2;
        }
    }

    // ---- KL: block 0 only (64x128 = 8192 elements over 128 threads) ----
    if (bid == 0) {
        __shared__ float kred[128];
        float kl = 0.f;
        for (int i = tid; i < NUM_GRAPHS * LATENT; i += 128) {
            float m = mu[i], lv = logvar[i];
            kl += 1.f + lv - m * m - expf(lv);
        }
        kred[tid] = kl;
        __syncthreads();
        #pragma unroll
        for (int s = 64; s > 0; s >>= 1) {
            if (tid < s) kred[tid] += kred[tid + s];
            __syncthreads();
        }
        if (tid == 0) g_kl = (double)kred[0];
    }

    // ---- persistent edge loop: 5 iters x 8 edges/thread, prefetched ----
    float s_d2 = 0.f, s_len = 0.f;
    #pragma unroll
    for (int it = 0; it < EITERS; it++) {
        int4 a0 = na0, a1 = na1, b0 = nb0, b1 = nb1;
        if (it + 1 < EITERS) {
            int gn = (it + 1) * (EBLOCKS * 128) + bid * 128 + tid;
            na0 = ei[2 * gn]; na1 = ei[2 * gn + 1];
            nb0 = ej[2 * gn]; nb1 = ej[2 * gn + 1];
        }

        int ia[8] = {a0.x, a0.y, a0.z, a0.w, a1.x, a1.y, a1.z, a1.w};
        int ib[8] = {b0.x, b0.y, b0.z, b0.w, b1.x, b1.y, b1.z, b1.w};

        float2 pi[8], pj[8];
        #pragma unroll
        for (int k = 0; k < 8; k++) {
            pi[k] = __ldg(&pred[ia[k]]);
            pj[k] = __ldg(&pred[ib[k]]);
        }

        #pragma unroll
        for (int k = 0; k < 8; k++) {
            float dx = pi[k].x - pj[k].x;
            float dy = pi[k].y - pj[k].y;
            float d2 = fmaf(dx, dx, dy * dy);
            float len;
            asm("sqrt.approx.f32 %0, %1;" : "=f"(len) : "f"(d2));
            s_d2  += d2;
            s_len += len;
        }
    }

    // ---- block reduce edge sums + recon, one double atomic each ----
    #pragma unroll
    for (int o = 16; o > 0; o >>= 1) {
        s_d2  += __shfl_down_sync(FULL, s_d2, o);
        s_len += __shfl_down_sync(FULL, s_len, o);
    }
    if (l == 0) { smd2[w] = s_d2; smln[w] = s_len; }
    __syncthreads();
    if (tid == 0) {
        float d2 = 0.f, ln = 0.f, rc = 0.f;
        #pragma unroll
        for (int i = 0; i < 4; i++) { d2 += smd2[i]; ln += smln[i]; }
        #pragma unroll
        for (int i = 0; i < 5; i++) rc += sred[i];
        atomicAdd(&g_sumd2, (double)d2);
        atomicAdd(&g_sumlen, (double)ln);
        atomicAdd(&g_recon, (double)rc);
    }

    // ---- completion protocol: last block finalizes ----
    __syncthreads();
    __shared__ bool s_last;
    if (tid == 0) {
        __threadfence();                 // release: my atomics before counter
        unsigned old = atomicAdd(&g_count, 1u);
        s_last = (old == EBLOCKS - 1);
    }
    __syncthreads();

    if (s_last) {
        __threadfence();                 // acquire: see all blocks' atomics
        __shared__ double dred[NUM_GRAPHS];
        if (tid < NUM_GRAPHS) {
            double c  = (double)__ldcg(&g_gcnt[tid]);
            double mx = (double)__ldcg(&g_gsum[2 * tid])     / c;
            double my = (double)__ldcg(&g_gsum[2 * tid + 1]) / c;
            dred[tid] = mx * mx + my * my;
        }
        __syncthreads();
        // reset per-graph accumulators for the next replay
        if (tid < NUM_GRAPHS) {
            g_gcnt[tid] = 0.f;
            g_gsum[2 * tid] = 0.f;
            g_gsum[2 * tid + 1] = 0.f;
        }
        if (tid == 0) {
            double drift = 0.0;
            #pragma unroll
            for (int gg = 0; gg < NUM_GRAPHS; gg++) drift += dred[gg];
            drift /= (double)NUM_GRAPHS;

            double sumd2  = __ldcg(&g_sumd2);
            double sumlen = __ldcg(&g_sumlen);
            double recon  = __ldcg(&g_recon) / (2.0 * (double)N_NODES);
            double klv    = -0.5 * __ldcg(&g_kl) / (double)NUM_GRAPHS;

            double lap     = sumd2 / (double)N_EDGES;
            double meanlen = sumlen / (double)N_EDGES;
            double arap    = (sumd2 - (double)N_EDGES * meanlen * meanlen)
                             / ((double)N_EDGES - 1.0);

            int ep = *epoch;
            double beta = (ep < 10) ? (double)ep / 10.0 : 1.0;

            out[0] = (float)(recon + 0.1 * lap + 0.01 * drift
                             + 0.1 * arap + beta * klv);

            // reset scalar accumulators + counter for the next replay
            g_recon = 0.0; g_sumd2 = 0.0; g_sumlen = 0.0; g_kl = 0.0;
            g_count = 0u;
        }
    }
}

extern "C" void kernel_launch(void* const* d_in, const int* in_sizes, int n_in,
                              void* d_out, int out_size) {
    const float* pred   = (const float*)d_in[0];
    const float* target = (const float*)d_in[1];
    const int*   edges  = (const int*)d_in[2];
    const int*   batch  = (const int*)d_in[3];
    const float* mu     = (const float*)d_in[4];
    const float* logvar = (const float*)d_in[5];
    const int*   epoch  = (const int*)d_in[6];
    float* out = (float*)d_out;

    fused_kernel<<<EBLOCKS, 128>>>(
        (const float4*)pred, (const float4*)target, (const int2*)batch,
        (const int4*)edges, (const int4*)(edges + N_EDGES),
        (const float2*)pred, mu, logvar, epoch, out);
}

// round 8
// speedup vs baseline: 1.0124x; 1.0124x over previous
#include <cuda_runtime.h>

#define N_NODES    1000000
#define N_EDGES    16000000
#define NUM_GRAPHS 64
#define LATENT     128
#define NBLOCKS    15625     // 16M edges / (128 thr * 8 edges)

// Global accumulators (zero-initialized at module load; the final block
// re-zeros everything so each graph replay starts clean).
__device__ double   g_recon;
__device__ double   g_sumd2;
__device__ double   g_sumlen;
__device__ double   g_kl;
__device__ float    g_gsum[2 * NUM_GRAPHS];
__device__ float    g_gcnt[NUM_GRAPHS];
__device__ unsigned g_count;

// ---------------------------------------------------------------------------
// One fused kernel (one-shot blocks; forced 16 blocks/SM for 100% occupancy):
//   - every block: 1024 edges (8/thread, 16 front-batched L2 gathers/thread)
//   - warp 0 of every block: 32 node-pairs (recon MSE + drift segment sums)
//   - block 0: KL over 64x128
//   - last block to finish (threadfence + counter): finalize + reset
// ---------------------------------------------------------------------------
__global__ void __launch_bounds__(128, 16)
fused_kernel(const float4* __restrict__ pred4,
             const float4* __restrict__ tgt4,
             const int2*  __restrict__ batch2,
             const int4*  __restrict__ ei,
             const int4*  __restrict__ ej,
             const float2* __restrict__ pred,
             const float* __restrict__ mu,
             const float* __restrict__ logvar,
             const int*  __restrict__ epoch,
             float* __restrict__ out) {
    const int tid = threadIdx.x;
    const int bid = blockIdx.x;
    const int l   = tid & 31;
    const int w   = tid >> 5;
    const unsigned FULL = 0xffffffffu;

    // ---- edge index loads first (long-latency DRAM, front-batched) ----
    const int t = bid * 128 + tid;
    int4 a0 = ei[2 * t], a1 = ei[2 * t + 1];
    int4 b0 = ej[2 * t], b1 = ej[2 * t + 1];

    // ---- node pass: warp 0 handles 32 float4-pairs (15625*32 = 500k exact) ----
    float rec_part = 0.f;            // valid in tid 0 only after reduce
    if (tid < 32) {
        int idx  = bid * 32 + tid;
        float4 p = pred4[idx];
        float4 q = tgt4[idx];
        int2   b = batch2[idx];

        float dx0 = p.x - q.x, dy0 = p.y - q.y;
        float dx1 = p.z - q.z, dy1 = p.w - q.w;
        float rec = dx0 * dx0 + dy0 * dy0 + dx1 * dx1 + dy1 * dy1;
        #pragma unroll
        for (int o = 16; o > 0; o >>= 1)
            rec += __shfl_down_sync(FULL, rec, o);
        rec_part = rec;

        int g0   = __shfl_sync(FULL, b.x, 0);
        bool uni = __all_sync(FULL, (b.x == g0) && (b.y == g0));
        if (uni) {
            float sx = p.x + p.z;
            float sy = p.y + p.w;
            #pragma unroll
            for (int o = 16; o > 0; o >>= 1) {
                sx += __shfl_down_sync(FULL, sx, o);
                sy += __shfl_down_sync(FULL, sy, o);
            }
            if (l == 0) {
                atomicAdd(&g_gsum[2 * g0],     sx);
                atomicAdd(&g_gsum[2 * g0 + 1], sy);
                atomicAdd(&g_gcnt[g0], 64.f);          // 32 lanes x 2 nodes
            }
        } else {
            // boundary warp (graph id changes inside warp) — rare
            atomicAdd(&g_gsum[2 * b.x],     p.x);
            atomicAdd(&g_gsum[2 * b.x + 1], p.y);
            atomicAdd(&g_gcnt[b.x], 1.f);
            atomicAdd(&g_gsum[2 * b.y],     p.z);
            atomicAdd(&g_gsum[2 * b.y + 1], p.w);
            atomicAdd(&g_gcnt[b.y], 1.f);
            __threadfence();   // order these atomics before the done-counter
        }
    }

    // ---- KL: block 0 only (64x128 = 8192 elements over 128 threads) ----
    if (bid == 0) {
        __shared__ float kred[128];
        float kl = 0.f;
        for (int i = tid; i < NUM_GRAPHS * LATENT; i += 128) {
            float m = mu[i], lv = logvar[i];
            kl += 1.f + lv - m * m - expf(lv);
        }
        kred[tid] = kl;
        __syncthreads();
        #pragma unroll
        for (int s = 64; s > 0; s >>= 1) {
            if (tid < s) kred[tid] += kred[tid + s];
            __syncthreads();
        }
        if (tid == 0) g_kl = (double)kred[0];
    }

    // ---- edge pass: 8 edges/thread, 16 random gathers front-batched ----
    int ia[8] = {a0.x, a0.y, a0.z, a0.w, a1.x, a1.y, a1.z, a1.w};
    int ib[8] = {b0.x, b0.y, b0.z, b0.w, b1.x, b1.y, b1.z, b1.w};

    float2 pi[8], pj[8];
    #pragma unroll
    for (int k = 0; k < 8; k++) {
        pi[k] = __ldg(&pred[ia[k]]);
        pj[k] = __ldg(&pred[ib[k]]);
    }

    float s_d2 = 0.f, s_len = 0.f;
    #pragma unroll
    for (int k = 0; k < 8; k++) {
        float dx = pi[k].x - pj[k].x;
        float dy = pi[k].y - pj[k].y;
        float d2 = fmaf(dx, dx, dy * dy);
        float len;
        asm("sqrt.approx.f32 %0, %1;" : "=f"(len) : "f"(d2));
        s_d2  += d2;
        s_len += len;
    }

    #pragma unroll
    for (int o = 16; o > 0; o >>= 1) {
        s_d2  += __shfl_down_sync(FULL, s_d2, o);
        s_len += __shfl_down_sync(FULL, s_len, o);
    }
    __shared__ float smd2[4], smln[4];
    if (l == 0) { smd2[w] = s_d2; smln[w] = s_len; }
    __syncthreads();
    if (tid == 0) {
        float d2 = 0.f, ln = 0.f;
        #pragma unroll
        for (int i = 0; i < 4; i++) { d2 += smd2[i]; ln += smln[i]; }
        atomicAdd(&g_sumd2, (double)d2);
        atomicAdd(&g_sumlen, (double)ln);
        atomicAdd(&g_recon, (double)rec_part);
    }

    // ---- completion protocol: last block finalizes ----
    __syncthreads();
    __shared__ bool s_last;
    if (tid == 0) {
        __threadfence();                 // release: my atomics before counter
        unsigned old = atomicAdd(&g_count, 1u);
        s_last = (old == NBLOCKS - 1);
    }
    __syncthreads();

    if (s_last) {
        __threadfence();                 // acquire: see all blocks' atomics
        __shared__ double dred[NUM_GRAPHS];
        if (tid < NUM_GRAPHS) {
            double c  = (double)__ldcg(&g_gcnt[tid]);
            double mx = (double)__ldcg(&g_gsum[2 * tid])     / c;
            double my = (double)__ldcg(&g_gsum[2 * tid + 1]) / c;
            dred[tid] = mx * mx + my * my;
        }
        __syncthreads();
        // reset per-graph accumulators for the next replay
        if (tid < NUM_GRAPHS) {
            g_gcnt[tid] = 0.f;
            g_gsum[2 * tid] = 0.f;
            g_gsum[2 * tid + 1] = 0.f;
        }
        if (tid == 0) {
            double drift = 0.0;
            #pragma unroll
            for (int gg = 0; gg < NUM_GRAPHS; gg++) drift += dred[gg];
            drift /= (double)NUM_GRAPHS;

            double sumd2  = __ldcg(&g_sumd2);
            double sumlen = __ldcg(&g_sumlen);
            double recon  = __ldcg(&g_recon) / (2.0 * (double)N_NODES);
            double klv    = -0.5 * __ldcg(&g_kl) / (double)NUM_GRAPHS;

            double lap     = sumd2 / (double)N_EDGES;
            double meanlen = sumlen / (double)N_EDGES;
            double arap    = (sumd2 - (double)N_EDGES * meanlen * meanlen)
                             / ((double)N_EDGES - 1.0);

            int ep = *epoch;
            double beta = (ep < 10) ? (double)ep / 10.0 : 1.0;

            out[0] = (float)(recon + 0.1 * lap + 0.01 * drift
                             + 0.1 * arap + beta * klv);

            // reset scalar accumulators + counter for the next replay
            g_recon = 0.0; g_sumd2 = 0.0; g_sumlen = 0.0; g_kl = 0.0;
            g_count = 0u;
        }
    }
}

extern "C" void kernel_launch(void* const* d_in, const int* in_sizes, int n_in,
                              void* d_out, int out_size) {
    const float* pred   = (const float*)d_in[0];
    const float* target = (const float*)d_in[1];
    const int*   edges  = (const int*)d_in[2];
    const int*   batch  = (const int*)d_in[3];
    const float* mu     = (const float*)d_in[4];
    const float* logvar = (const float*)d_in[5];
    const int*   epoch  = (const int*)d_in[6];
    float* out = (float*)d_out;

    fused_kernel<<<NBLOCKS, 128>>>(
        (const float4*)pred, (const float4*)target, (const int2*)batch,
        (const int4*)edges, (const int4*)(edges + N_EDGES),
        (const float2*)pred, mu, logvar, epoch, out);
}

// round 9
// speedup vs baseline: 1.0126x; 1.0002x over previous
#include <cuda_runtime.h>

#define N_NODES    1000000
#define N_EDGES    16000000
#define NUM_GRAPHS 64
#define LATENT     128
#define NBLOCKS    15625     // 16M edges / (256 thr * 4 edges)

// Global accumulators (zero-initialized at module load; the final block
// re-zeros everything so each graph replay starts clean).
__device__ double   g_recon;
__device__ double   g_sumd2;
__device__ double   g_sumlen;
__device__ double   g_kl;
__device__ float    g_gsum[2 * NUM_GRAPHS];
__device__ float    g_gcnt[NUM_GRAPHS];
__device__ unsigned g_count;

// ---------------------------------------------------------------------------
// One fused kernel (one-shot blocks, 256 thr x 4 edges: low reg pressure,
// no spills, ~87% occupancy):
//   - every block: 1024 edges (4/thread, 8 front-batched L2 gathers/thread)
//   - warp 0 of every block: 32 node-pairs (recon MSE + drift segment sums)
//   - block 0: KL over 64x128
//   - last block to finish (threadfence + counter): finalize + reset
// ---------------------------------------------------------------------------
__global__ void __launch_bounds__(256)
fused_kernel(const float4* __restrict__ pred4,
             const float4* __restrict__ tgt4,
             const int2*  __restrict__ batch2,
             const int4*  __restrict__ ei,
             const int4*  __restrict__ ej,
             const float2* __restrict__ pred,
             const float* __restrict__ mu,
             const float* __restrict__ logvar,
             const int*  __restrict__ epoch,
             float* __restrict__ out) {
    const int tid = threadIdx.x;
    const int bid = blockIdx.x;
    const int l   = tid & 31;
    const int w   = tid >> 5;
    const unsigned FULL = 0xffffffffu;

    // ---- edge index loads first (long-latency DRAM, front-batched) ----
    const int t = bid * 256 + tid;
    int4 a = ei[t];
    int4 b = ej[t];

    // ---- node pass: warp 0 handles 32 float4-pairs (15625*32 = 500k exact) ----
    float rec_part = 0.f;            // valid in tid 0 only after reduce
    if (tid < 32) {
        int idx  = bid * 32 + tid;
        float4 p = pred4[idx];
        float4 q = tgt4[idx];
        int2   bb = batch2[idx];

        float dx0 = p.x - q.x, dy0 = p.y - q.y;
        float dx1 = p.z - q.z, dy1 = p.w - q.w;
        float rec = dx0 * dx0 + dy0 * dy0 + dx1 * dx1 + dy1 * dy1;
        #pragma unroll
        for (int o = 16; o > 0; o >>= 1)
            rec += __shfl_down_sync(FULL, rec, o);
        rec_part = rec;

        int g0   = __shfl_sync(FULL, bb.x, 0);
        bool uni = __all_sync(FULL, (bb.x == g0) && (bb.y == g0));
        if (uni) {
            float sx = p.x + p.z;
            float sy = p.y + p.w;
            #pragma unroll
            for (int o = 16; o > 0; o >>= 1) {
                sx += __shfl_down_sync(FULL, sx, o);
                sy += __shfl_down_sync(FULL, sy, o);
            }
            if (l == 0) {
                atomicAdd(&g_gsum[2 * g0],     sx);
                atomicAdd(&g_gsum[2 * g0 + 1], sy);
                atomicAdd(&g_gcnt[g0], 64.f);          // 32 lanes x 2 nodes
            }
        } else {
            // boundary warp (graph id changes inside warp) — rare
            atomicAdd(&g_gsum[2 * bb.x],     p.x);
            atomicAdd(&g_gsum[2 * bb.x + 1], p.y);
            atomicAdd(&g_gcnt[bb.x], 1.f);
            atomicAdd(&g_gsum[2 * bb.y],     p.z);
            atomicAdd(&g_gsum[2 * bb.y + 1], p.w);
            atomicAdd(&g_gcnt[bb.y], 1.f);
            __threadfence();   // order these atomics before the done-counter
        }
    }

    // ---- KL: block 0 only (64x128 = 8192 elements over 256 threads) ----
    if (bid == 0) {
        __shared__ float kred[256];
        float kl = 0.f;
        for (int i = tid; i < NUM_GRAPHS * LATENT; i += 256) {
            float m = mu[i], lv = logvar[i];
            kl += 1.f + lv - m * m - expf(lv);
        }
        kred[tid] = kl;
        __syncthreads();
        #pragma unroll
        for (int s = 128; s > 0; s >>= 1) {
            if (tid < s) kred[tid] += kred[tid + s];
            __syncthreads();
        }
        if (tid == 0) g_kl = (double)kred[0];
    }

    // ---- edge pass: 4 edges/thread, 8 random gathers front-batched ----
    int ia[4] = {a.x, a.y, a.z, a.w};
    int ib[4] = {b.x, b.y, b.z, b.w};

    float2 pi[4], pj[4];
    #pragma unroll
    for (int k = 0; k < 4; k++) {
        pi[k] = __ldg(&pred[ia[k]]);
        pj[k] = __ldg(&pred[ib[k]]);
    }

    float s_d2 = 0.f, s_len = 0.f;
    #pragma unroll
    for (int k = 0; k < 4; k++) {
        float dx = pi[k].x - pj[k].x;
        float dy = pi[k].y - pj[k].y;
        float d2 = fmaf(dx, dx, dy * dy);
        float len;
        asm("sqrt.approx.f32 %0, %1;" : "=f"(len) : "f"(d2));
        s_d2  += d2;
        s_len += len;
    }

    #pragma unroll
    for (int o = 16; o > 0; o >>= 1) {
        s_d2  += __shfl_down_sync(FULL, s_d2, o);
        s_len += __shfl_down_sync(FULL, s_len, o);
    }
    __shared__ float smd2[8], smln[8];
    if (l == 0) { smd2[w] = s_d2; smln[w] = s_len; }
    __syncthreads();
    if (tid == 0) {
        float d2 = 0.f, ln = 0.f;
        #pragma unroll
        for (int i = 0; i < 8; i++) { d2 += smd2[i]; ln += smln[i]; }
        atomicAdd(&g_sumd2, (double)d2);
        atomicAdd(&g_sumlen, (double)ln);
        atomicAdd(&g_recon, (double)rec_part);
    }

    // ---- completion protocol: last block finalizes ----
    __syncthreads();
    __shared__ bool s_last;
    if (tid == 0) {
        __threadfence();                 // release: my atomics before counter
        unsigned old = atomicAdd(&g_count, 1u);
        s_last = (old == NBLOCKS - 1);
    }
    __syncthreads();

    if (s_last) {
        __threadfence();                 // acquire: see all blocks' atomics
        __shared__ double dred[NUM_GRAPHS];
        if (tid < NUM_GRAPHS) {
            double c  = (double)__ldcg(&g_gcnt[tid]);
            double mx = (double)__ldcg(&g_gsum[2 * tid])     / c;
            double my = (double)__ldcg(&g_gsum[2 * tid + 1]) / c;
            dred[tid] = mx * mx + my * my;
        }
        __syncthreads();
        // reset per-graph accumulators for the next replay
        if (tid < NUM_GRAPHS) {
            g_gcnt[tid] = 0.f;
            g_gsum[2 * tid] = 0.f;
            g_gsum[2 * tid + 1] = 0.f;
        }
        if (tid == 0) {
            double drift = 0.0;
            #pragma unroll
            for (int gg = 0; gg < NUM_GRAPHS; gg++) drift += dred[gg];
            drift /= (double)NUM_GRAPHS;

            double sumd2  = __ldcg(&g_sumd2);
            double sumlen = __ldcg(&g_sumlen);
            double recon  = __ldcg(&g_recon) / (2.0 * (double)N_NODES);
            double klv    = -0.5 * __ldcg(&g_kl) / (double)NUM_GRAPHS;

            double lap     = sumd2 / (double)N_EDGES;
            double meanlen = sumlen / (double)N_EDGES;
            double arap    = (sumd2 - (double)N_EDGES * meanlen * meanlen)
                             / ((double)N_EDGES - 1.0);

            int ep = *epoch;
            double beta = (ep < 10) ? (double)ep / 10.0 : 1.0;

            out[0] = (float)(recon + 0.1 * lap + 0.01 * drift
                             + 0.1 * arap + beta * klv);

            // reset scalar accumulators + counter for the next replay
            g_recon = 0.0; g_sumd2 = 0.0; g_sumlen = 0.0; g_kl = 0.0;
            g_count = 0u;
        }
    }
}

extern "C" void kernel_launch(void* const* d_in, const int* in_sizes, int n_in,
                              void* d_out, int out_size) {
    const float* pred   = (const float*)d_in[0];
    const float* target = (const float*)d_in[1];
    const int*   edges  = (const int*)d_in[2];
    const int*   batch  = (const int*)d_in[3];
    const float* mu     = (const float*)d_in[4];
    const float* logvar = (const float*)d_in[5];
    const int*   epoch  = (const int*)d_in[6];
    float* out = (float*)d_out;

    fused_kernel<<<NBLOCKS, 256>>>(
        (const float4*)pred, (const float4*)target, (const int2*)batch,
        (const int4*)edges, (const int4*)(edges + N_EDGES),
        (const float2*)pred, mu, logvar, epoch, out);
}

// round 10
// speedup vs baseline: 1.0453x; 1.0323x over previous
#include <cuda_runtime.h>

#define N_NODES    1000000
#define N_EDGES    16000000
#define NUM_GRAPHS 64
#define LATENT     128
#define NBLOCKS    15625     // 16M edges / (128 thr * 8 edges)

// Global accumulators (zero-initialized at module load; the final block
// re-zeros everything so each graph replay starts clean).
__device__ double   g_recon;
__device__ double   g_sumd2;
__device__ double   g_sumlen;
__device__ double   g_kl;
__device__ float    g_gsum[2 * NUM_GRAPHS];
__device__ float    g_gcnt[NUM_GRAPHS];
__device__ unsigned g_count;

__device__ __forceinline__ float2 ldcg_f2(const float2* p) {
    float2 v;
    asm volatile("ld.global.cg.v2.f32 {%0,%1}, [%2];"
                 : "=f"(v.x), "=f"(v.y) : "l"(p));
    return v;
}
__device__ __forceinline__ int4 ldcs_i4(const int4* p) {
    int4 v;
    asm volatile("ld.global.cs.v4.s32 {%0,%1,%2,%3}, [%4];"
                 : "=r"(v.x), "=r"(v.y), "=r"(v.z), "=r"(v.w) : "l"(p));
    return v;
}
__device__ __forceinline__ float4 ldcs_f4(const float4* p) {
    float4 v;
    asm volatile("ld.global.cs.v4.f32 {%0,%1,%2,%3}, [%4];"
                 : "=f"(v.x), "=f"(v.y), "=f"(v.z), "=f"(v.w) : "l"(p));
    return v;
}

// ---------------------------------------------------------------------------
// One fused kernel (R6 structure: 128 thr x 8 edges, natural regs):
//   - gathers use ld.global.cg (L1-bypass: no allocation on the hot pipe)
//   - streaming index/node loads use ld.global.cs (evict-first)
//   - warp 0 of every block: 32 node-pairs (recon MSE + drift segment sums)
//   - block 0: KL over 64x128
//   - last block to finish (threadfence + counter): finalize + reset
// ---------------------------------------------------------------------------
__global__ void __launch_bounds__(128)
fused_kernel(const float4* __restrict__ pred4,
             const float4* __restrict__ tgt4,
             const int2*  __restrict__ batch2,
             const int4*  __restrict__ ei,
             const int4*  __restrict__ ej,
             const float2* __restrict__ pred,
             const float* __restrict__ mu,
             const float* __restrict__ logvar,
             const int*  __restrict__ epoch,
             float* __restrict__ out) {
    const int tid = threadIdx.x;
    const int bid = blockIdx.x;
    const int l   = tid & 31;
    const int w   = tid >> 5;
    const unsigned FULL = 0xffffffffu;

    // ---- edge index loads first (long-latency DRAM, front-batched) ----
    const int t = bid * 128 + tid;
    int4 a0 = ldcs_i4(&ei[2 * t]), a1 = ldcs_i4(&ei[2 * t + 1]);
    int4 b0 = ldcs_i4(&ej[2 * t]), b1 = ldcs_i4(&ej[2 * t + 1]);

    // ---- node pass: warp 0 handles 32 float4-pairs (15625*32 = 500k exact) ----
    float rec_part = 0.f;            // valid in tid 0 only after reduce
    if (tid < 32) {
        int idx  = bid * 32 + tid;
        float4 p = ldcs_f4(&pred4[idx]);
        float4 q = ldcs_f4(&tgt4[idx]);
        int2   b = batch2[idx];

        float dx0 = p.x - q.x, dy0 = p.y - q.y;
        float dx1 = p.z - q.z, dy1 = p.w - q.w;
        float rec = dx0 * dx0 + dy0 * dy0 + dx1 * dx1 + dy1 * dy1;
        #pragma unroll
        for (int o = 16; o > 0; o >>= 1)
            rec += __shfl_down_sync(FULL, rec, o);
        rec_part = rec;

        int g0   = __shfl_sync(FULL, b.x, 0);
        bool uni = __all_sync(FULL, (b.x == g0) && (b.y == g0));
        if (uni) {
            float sx = p.x + p.z;
            float sy = p.y + p.w;
            #pragma unroll
            for (int o = 16; o > 0; o >>= 1) {
                sx += __shfl_down_sync(FULL, sx, o);
                sy += __shfl_down_sync(FULL, sy, o);
            }
            if (l == 0) {
                atomicAdd(&g_gsum[2 * g0],     sx);
                atomicAdd(&g_gsum[2 * g0 + 1], sy);
                atomicAdd(&g_gcnt[g0], 64.f);          // 32 lanes x 2 nodes
            }
        } else {
            // boundary warp (graph id changes inside warp) — rare
            atomicAdd(&g_gsum[2 * b.x],     p.x);
            atomicAdd(&g_gsum[2 * b.x + 1], p.y);
            atomicAdd(&g_gcnt[b.x], 1.f);
            atomicAdd(&g_gsum[2 * b.y],     p.z);
            atomicAdd(&g_gsum[2 * b.y + 1], p.w);
            atomicAdd(&g_gcnt[b.y], 1.f);
            __threadfence();   // order these atomics before the done-counter
        }
    }

    // ---- KL: block 0 only (64x128 = 8192 elements over 128 threads) ----
    if (bid == 0) {
        __shared__ float kred[128];
        float kl = 0.f;
        for (int i = tid; i < NUM_GRAPHS * LATENT; i += 128) {
            float m = mu[i], lv = logvar[i];
            kl += 1.f + lv - m * m - expf(lv);
        }
        kred[tid] = kl;
        __syncthreads();
        #pragma unroll
        for (int s = 64; s > 0; s >>= 1) {
            if (tid < s) kred[tid] += kred[tid + s];
            __syncthreads();
        }
        if (tid == 0) g_kl = (double)kred[0];
    }

    // ---- edge pass: 8 edges/thread, 16 L1-bypass gathers front-batched ----
    int ia[8] = {a0.x, a0.y, a0.z, a0.w, a1.x, a1.y, a1.z, a1.w};
    int ib[8] = {b0.x, b0.y, b0.z, b0.w, b1.x, b1.y, b1.z, b1.w};

    float2 pi[8], pj[8];
    #pragma unroll
    for (int k = 0; k < 8; k++) {
        pi[k] = ldcg_f2(&pred[ia[k]]);
        pj[k] = ldcg_f2(&pred[ib[k]]);
    }

    float s_d2 = 0.f, s_len = 0.f;
    #pragma unroll
    for (int k = 0; k < 8; k++) {
        float dx = pi[k].x - pj[k].x;
        float dy = pi[k].y - pj[k].y;
        float d2 = fmaf(dx, dx, dy * dy);
        float len;
        asm("sqrt.approx.f32 %0, %1;" : "=f"(len) : "f"(d2));
        s_d2  += d2;
        s_len += len;
    }

    #pragma unroll
    for (int o = 16; o > 0; o >>= 1) {
        s_d2  += __shfl_down_sync(FULL, s_d2, o);
        s_len += __shfl_down_sync(FULL, s_len, o);
    }
    __shared__ float smd2[4], smln[4];
    if (l == 0) { smd2[w] = s_d2; smln[w] = s_len; }
    __syncthreads();
    if (tid == 0) {
        float d2 = 0.f, ln = 0.f;
        #pragma unroll
        for (int i = 0; i < 4; i++) { d2 += smd2[i]; ln += smln[i]; }
        atomicAdd(&g_sumd2, (double)d2);
        atomicAdd(&g_sumlen, (double)ln);
        atomicAdd(&g_recon, (double)rec_part);
    }

    // ---- completion protocol: last block finalizes ----
    __syncthreads();
    __shared__ bool s_last;
    if (tid == 0) {
        __threadfence();                 // release: my atomics before counter
        unsigned old = atomicAdd(&g_count, 1u);
        s_last = (old == NBLOCKS - 1);
    }
    __syncthreads();

    if (s_last) {
        __threadfence();                 // acquire: see all blocks' atomics
        __shared__ double dred[NUM_GRAPHS];
        if (tid < NUM_GRAPHS) {
            double c  = (double)__ldcg(&g_gcnt[tid]);
            double mx = (double)__ldcg(&g_gsum[2 * tid])     / c;
            double my = (double)__ldcg(&g_gsum[2 * tid + 1]) / c;
            dred[tid] = mx * mx + my * my;
        }
        __syncthreads();
        // reset per-graph accumulators for the next replay
        if (tid < NUM_GRAPHS) {
            g_gcnt[tid] = 0.f;
            g_gsum[2 * tid] = 0.f;
            g_gsum[2 * tid + 1] = 0.f;
        }
        if (tid == 0) {
            double drift = 0.0;
            #pragma unroll
            for (int gg = 0; gg < NUM_GRAPHS; gg++) drift += dred[gg];
            drift /= (double)NUM_GRAPHS;

            double sumd2  = __ldcg(&g_sumd2);
            double sumlen = __ldcg(&g_sumlen);
            double recon  = __ldcg(&g_recon) / (2.0 * (double)N_NODES);
            double klv    = -0.5 * __ldcg(&g_kl) / (double)NUM_GRAPHS;

            double lap     = sumd2 / (double)N_EDGES;
            double meanlen = sumlen / (double)N_EDGES;
            double arap    = (sumd2 - (double)N_EDGES * meanlen * meanlen)
                             / ((double)N_EDGES - 1.0);

            int ep = *epoch;
            double beta = (ep < 10) ? (double)ep / 10.0 : 1.0;

            out[0] = (float)(recon + 0.1 * lap + 0.01 * drift
                             + 0.1 * arap + beta * klv);

            // reset scalar accumulators + counter for the next replay
            g_recon = 0.0; g_sumd2 = 0.0; g_sumlen = 0.0; g_kl = 0.0;
            g_count = 0u;
        }
    }
}

extern "C" void kernel_launch(void* const* d_in, const int* in_sizes, int n_in,
                              void* d_out, int out_size) {
    const float* pred   = (const float*)d_in[0];
    const float* target = (const float*)d_in[1];
    const int*   edges  = (const int*)d_in[2];
    const int*   batch  = (const int*)d_in[3];
    const float* mu     = (const float*)d_in[4];
    const float* logvar = (const float*)d_in[5];
    const int*   epoch  = (const int*)d_in[6];
    float* out = (float*)d_out;

    fused_kernel<<<NBLOCKS, 128>>>(
        (const float4*)pred, (const float4*)target, (const int2*)batch,
        (const int4*)edges, (const int4*)(edges + N_EDGES),
        (const float2*)pred, mu, logvar, epoch, out);
}